// round 4
// baseline (speedup 1.0000x reference)
#include <cuda_runtime.h>
#include <stdint.h>

#define NEG_INF (__int_as_float(0xff800000))

#define Bc 2
#define Sc 4096
#define Ec 768
#define Hc 12
#define HDc 64
#define Wc 256
#define Gc 32
#define Mrows (Bc*Sc)   /* 8192 */

// ---------------- scratch (device globals; no allocation allowed) ----------------
__device__ float g_q [Mrows*Ec];
__device__ float g_k [Mrows*Ec];
__device__ float g_v [Mrows*Ec];
__device__ float g_kg[Mrows*Ec];
__device__ float g_vg[Mrows*Ec];
__device__ float g_qg[Bc*Gc*Ec];
__device__ float g_gw[(size_t)Bc*Hc*Gc*Sc];
__device__ float g_gattn[Bc*Gc*Ec];

// ---------------- tf32 helpers ----------------
__device__ __forceinline__ float f2tf32(float x) {
    float r;
    asm("cvt.rna.tf32.f32 %0, %1;" : "=f"(r) : "f"(x));
    return r;
}

__device__ __forceinline__ void mma_tf32(float* d,
                                         const uint32_t* a,
                                         const uint32_t* b) {
    asm volatile(
        "mma.sync.aligned.m16n8k8.row.col.f32.tf32.tf32.f32 "
        "{%0,%1,%2,%3},{%4,%5,%6,%7},{%8,%9},{%0,%1,%2,%3};"
        : "+f"(d[0]), "+f"(d[1]), "+f"(d[2]), "+f"(d[3])
        : "r"(a[0]), "r"(a[1]), "r"(a[2]), "r"(a[3]), "r"(b[0]), "r"(b[1]));
}

// ---------------- 1) projection GEMMs on tensor cores (3xTF32 split) ----------------
// C[8192,768] = (A[8192,768] @ W[768,768] + bias) * scale
// 128x128x16 block tile, 8 warps (2m x 4n), warp tile 64x32 via m16n8k8.
#define SSTR 136   /* smem row stride: 136 % 32 == 8 -> conflict-free frag loads */

__global__ __launch_bounds__(256) void proj_tf32(
    const float* __restrict__ x,
    const float* __restrict__ w0, const float* __restrict__ b0,
    const float* __restrict__ w1, const float* __restrict__ b1,
    const float* __restrict__ w2, const float* __restrict__ b2,
    const float* __restrict__ w3, const float* __restrict__ b3,
    const float* __restrict__ w4, const float* __restrict__ b4)
{
    const float* W; const float* bias; float* out; float scale = 1.0f;
    switch (blockIdx.z) {
      case 0: W = w0; bias = b0; out = g_q;  scale = 0.125f; break;
      case 1: W = w1; bias = b1; out = g_k;  break;
      case 2: W = w2; bias = b2; out = g_v;  break;
      case 3: W = w3; bias = b3; out = g_kg; break;
      default:W = w4; bias = b4; out = g_vg; break;
    }
    const int m0 = blockIdx.y * 128;
    const int n0 = blockIdx.x * 128;

    __shared__ float Ah[16][SSTR];
    __shared__ float Al[16][SSTR];
    __shared__ float Bh[16][SSTR];
    __shared__ float Bl[16][SSTR];

    const int t    = threadIdx.x;
    const int lane = t & 31;
    const int warp = t >> 5;
    const int gid  = lane >> 2;    // 0..7
    const int tig  = lane & 3;     // 0..3
    const int mbase = (warp & 1) * 64;
    const int nbase = (warp >> 1) * 32;

    // global load assignment
    const int am  = t & 127;        // A row within tile
    const int ak  = (t >> 7) * 8;   // 0 or 8 (k half)
    const int bkr = warp;           // B k-row 0..7 (and +8)
    const int bn  = lane * 4;       // B n offset

    const float* Agp = x + (size_t)(m0 + am) * Ec + ak;
    const float* Bgp = W + n0 + bn;

    float acc[4][4][4];
    #pragma unroll
    for (int mt = 0; mt < 4; mt++)
      #pragma unroll
      for (int nt = 0; nt < 4; nt++)
        #pragma unroll
        for (int i = 0; i < 4; i++) acc[mt][nt][i] = 0.0f;

    float4 av0 = *(const float4*)(Agp);
    float4 av1 = *(const float4*)(Agp + 4);
    float4 bv0 = *(const float4*)(Bgp + (size_t)bkr * Ec);
    float4 bv1 = *(const float4*)(Bgp + (size_t)(bkr + 8) * Ec);

    for (int kt = 0; kt < Ec; kt += 16) {
        __syncthreads();
        // A: transpose-store with hi/lo split
        {
            float a8[8] = {av0.x, av0.y, av0.z, av0.w, av1.x, av1.y, av1.z, av1.w};
            #pragma unroll
            for (int j = 0; j < 8; j++) {
                float hi = f2tf32(a8[j]);
                Ah[ak + j][am] = hi;
                Al[ak + j][am] = f2tf32(a8[j] - hi);
            }
        }
        // B: row-store with hi/lo split (vectorized)
        {
            float4 h, l;
            h.x = f2tf32(bv0.x); l.x = f2tf32(bv0.x - h.x);
            h.y = f2tf32(bv0.y); l.y = f2tf32(bv0.y - h.y);
            h.z = f2tf32(bv0.z); l.z = f2tf32(bv0.z - h.z);
            h.w = f2tf32(bv0.w); l.w = f2tf32(bv0.w - h.w);
            *(float4*)&Bh[bkr][bn] = h;
            *(float4*)&Bl[bkr][bn] = l;
            h.x = f2tf32(bv1.x); l.x = f2tf32(bv1.x - h.x);
            h.y = f2tf32(bv1.y); l.y = f2tf32(bv1.y - h.y);
            h.z = f2tf32(bv1.z); l.z = f2tf32(bv1.z - h.z);
            h.w = f2tf32(bv1.w); l.w = f2tf32(bv1.w - h.w);
            *(float4*)&Bh[bkr + 8][bn] = h;
            *(float4*)&Bl[bkr + 8][bn] = l;
        }
        __syncthreads();

        if (kt + 16 < Ec) {
            av0 = *(const float4*)(Agp + kt + 16);
            av1 = *(const float4*)(Agp + kt + 20);
            bv0 = *(const float4*)(Bgp + (size_t)(kt + 16 + bkr) * Ec);
            bv1 = *(const float4*)(Bgp + (size_t)(kt + 24 + bkr) * Ec);
        }

        #pragma unroll
        for (int k8 = 0; k8 < 16; k8 += 8) {
            uint32_t afr[4][4], bhf[4][2], blf[4][2];
            #pragma unroll
            for (int mt = 0; mt < 4; mt++) {
                const int m = mbase + mt * 16 + gid;
                afr[mt][0] = *(const uint32_t*)&Ah[k8 + tig][m];
                afr[mt][1] = *(const uint32_t*)&Ah[k8 + tig][m + 8];
                afr[mt][2] = *(const uint32_t*)&Ah[k8 + tig + 4][m];
                afr[mt][3] = *(const uint32_t*)&Ah[k8 + tig + 4][m + 8];
            }
            #pragma unroll
            for (int nt = 0; nt < 4; nt++) {
                const int n = nbase + nt * 8 + gid;
                bhf[nt][0] = *(const uint32_t*)&Bh[k8 + tig][n];
                bhf[nt][1] = *(const uint32_t*)&Bh[k8 + tig + 4][n];
                blf[nt][0] = *(const uint32_t*)&Bl[k8 + tig][n];
                blf[nt][1] = *(const uint32_t*)&Bl[k8 + tig + 4][n];
            }
            // hi*hi + hi*lo
            #pragma unroll
            for (int mt = 0; mt < 4; mt++)
              #pragma unroll
              for (int nt = 0; nt < 4; nt++) {
                  mma_tf32(acc[mt][nt], afr[mt], bhf[nt]);
                  mma_tf32(acc[mt][nt], afr[mt], blf[nt]);
              }
            // lo*hi (reuse afr regs)
            #pragma unroll
            for (int mt = 0; mt < 4; mt++) {
                const int m = mbase + mt * 16 + gid;
                afr[mt][0] = *(const uint32_t*)&Al[k8 + tig][m];
                afr[mt][1] = *(const uint32_t*)&Al[k8 + tig][m + 8];
                afr[mt][2] = *(const uint32_t*)&Al[k8 + tig + 4][m];
                afr[mt][3] = *(const uint32_t*)&Al[k8 + tig + 4][m + 8];
            }
            #pragma unroll
            for (int mt = 0; mt < 4; mt++)
              #pragma unroll
              for (int nt = 0; nt < 4; nt++)
                  mma_tf32(acc[mt][nt], afr[mt], bhf[nt]);
        }
    }

    // epilogue: bias + scale
    #pragma unroll
    for (int mt = 0; mt < 4; mt++) {
        const int r = m0 + mbase + mt * 16 + gid;
        #pragma unroll
        for (int nt = 0; nt < 4; nt++) {
            const int c = n0 + nbase + nt * 8 + 2 * tig;
            const float bb0 = bias[c], bb1 = bias[c + 1];
            float2 o0 = make_float2((acc[mt][nt][0] + bb0) * scale,
                                    (acc[mt][nt][1] + bb1) * scale);
            float2 o1 = make_float2((acc[mt][nt][2] + bb0) * scale,
                                    (acc[mt][nt][3] + bb1) * scale);
            *(float2*)&out[(size_t)r * Ec + c] = o0;
            *(float2*)&out[(size_t)(r + 8) * Ec + c] = o1;
        }
    }
}

// ---------------- 2) qg (tiny GEMM over first G rows of each batch) ----------------
__global__ __launch_bounds__(256) void qg_gemm(const float* __restrict__ x,
                                               const float* __restrict__ w,
                                               const float* __restrict__ bias)
{
    const int m = blockIdx.x;           // 0..63
    const int b = m >> 5, g = m & 31;
    const float* xr = x + (size_t)(b * Sc + g) * Ec;
    __shared__ float xs[Ec];
    const int t = threadIdx.x;
    xs[t] = xr[t]; xs[t + 256] = xr[t + 256]; xs[t + 512] = xr[t + 512];
    __syncthreads();
    float a0 = 0.f, a1 = 0.f, a2 = 0.f;
    for (int k = 0; k < Ec; k++) {
        const float xv = xs[k];
        const float* wr = w + (size_t)k * Ec;
        a0 += xv * wr[t];
        a1 += xv * wr[t + 256];
        a2 += xv * wr[t + 512];
    }
    float* o = g_qg + (size_t)m * Ec;
    o[t]       = (a0 + bias[t])       * 0.125f;
    o[t + 256] = (a1 + bias[t + 256]) * 0.125f;
    o[t + 512] = (a2 + bias[t + 512]) * 0.125f;
}

// ---------------- 3) banded + global flash attention ----------------
// Block = (64-query tile, head, batch). Tiles: [sel G keys] + 9 band tiles of 64.
__global__ __launch_bounds__(256) void flash_banded(const int* __restrict__ mask,
                                                    float* __restrict__ out)
{
    const int q0 = blockIdx.x * 64;
    const int h  = blockIdx.y;
    const int b  = blockIdx.z;

    __shared__ float Qs[64 * 64];   // [d][r]
    __shared__ float KPs[64 * 64];  // K as [d][c], then reused as P [r][c]
    __shared__ float Vs[64 * 64];   // [c][d]

    const int t    = threadIdx.x;
    const int tx   = t & 15, ty = t >> 4;
    const int lane = t & 31, wrp = t >> 5;

    // load Q tile (transposed into Qs)
    {
        const int lr = t >> 2, ld = (t & 3) * 16;
        const float* qp = g_q + (size_t)(b * Sc + q0 + lr) * Ec + h * 64 + ld;
        #pragma unroll
        for (int u = 0; u < 4; u++) {
            float4 v = *(const float4*)(qp + 4 * u);
            Qs[(ld + 4 * u + 0) * 64 + lr] = v.x;
            Qs[(ld + 4 * u + 1) * 64 + lr] = v.y;
            Qs[(ld + 4 * u + 2) * 64 + lr] = v.z;
            Qs[(ld + 4 * u + 3) * 64 + lr] = v.w;
        }
    }

    float m8[8], l8[8];
    #pragma unroll
    for (int i = 0; i < 8; i++) { m8[i] = NEG_INF; l8[i] = 0.0f; }
    float O[4][4];
    #pragma unroll
    for (int i = 0; i < 4; i++)
      #pragma unroll
      for (int j = 0; j < 4; j++) O[i][j] = 0.0f;

    for (int tt = 0; tt < 10; tt++) {
        const bool is_sel = (tt == 0);
        const int tstart = is_sel ? 0 : (q0 - Wc + (tt - 1) * 64);

        __syncthreads();  // previous PV reads finished
        // load K, V tile
        {
            const int lr = t >> 2, ld = (t & 3) * 16;
            const int p = tstart + lr;
            if (p >= 0 && p < Sc) {
                const float* kp = g_k + (size_t)(b * Sc + p) * Ec + h * 64 + ld;
                const float* vp = g_v + (size_t)(b * Sc + p) * Ec + h * 64 + ld;
                #pragma unroll
                for (int u = 0; u < 4; u++) {
                    float4 kv = *(const float4*)(kp + 4 * u);
                    KPs[(ld + 4 * u + 0) * 64 + lr] = kv.x;
                    KPs[(ld + 4 * u + 1) * 64 + lr] = kv.y;
                    KPs[(ld + 4 * u + 2) * 64 + lr] = kv.z;
                    KPs[(ld + 4 * u + 3) * 64 + lr] = kv.w;
                    *(float4*)&Vs[lr * 64 + ld + 4 * u] = *(const float4*)(vp + 4 * u);
                }
            } else {
                const float4 z4 = make_float4(0.f, 0.f, 0.f, 0.f);
                #pragma unroll
                for (int u = 0; u < 4; u++) {
                    KPs[(ld + 4 * u + 0) * 64 + lr] = 0.f;
                    KPs[(ld + 4 * u + 1) * 64 + lr] = 0.f;
                    KPs[(ld + 4 * u + 2) * 64 + lr] = 0.f;
                    KPs[(ld + 4 * u + 3) * 64 + lr] = 0.f;
                    *(float4*)&Vs[lr * 64 + ld + 4 * u] = z4;
                }
            }
        }
        __syncthreads();

        // QK^T: s[i][j] = sum_d Q[r][d] K[c][d]
        float s[4][4];
        #pragma unroll
        for (int i = 0; i < 4; i++)
          #pragma unroll
          for (int j = 0; j < 4; j++) s[i][j] = 0.0f;
        #pragma unroll
        for (int d = 0; d < 64; d++) {
            float4 q4 = *(const float4*)&Qs[d * 64 + ty * 4];
            float4 k4 = *(const float4*)&KPs[d * 64 + tx * 4];
            float qa[4] = {q4.x, q4.y, q4.z, q4.w};
            float ka[4] = {k4.x, k4.y, k4.z, k4.w};
            #pragma unroll
            for (int i = 0; i < 4; i++)
              #pragma unroll
              for (int j = 0; j < 4; j++) s[i][j] += qa[i] * ka[j];
        }
        __syncthreads();  // done reading K
        // write raw scores into P buffer as [r][c]
        #pragma unroll
        for (int i = 0; i < 4; i++)
            *(float4*)&KPs[(ty * 4 + i) * 64 + tx * 4] =
                make_float4(s[i][0], s[i][1], s[i][2], s[i][3]);
        __syncthreads();

        // softmax: warp wrp owns rows 8*wrp .. 8*wrp+7; lane owns cols lane, lane+32
        const int c1 = lane, c2 = lane + 32;
        float bias1 = 0.f, bias2 = 0.f;
        bool v1base, v2base;
        if (is_sel) {
            v1base = (c1 < Gc);
            v2base = false;
        } else {
            const int p1 = tstart + c1, p2 = tstart + c2;
            v1base = (p1 >= 0 && p1 < Sc);
            v2base = (p2 >= 0 && p2 < Sc);
            if (v1base && mask[b * Sc + p1] != 0) bias1 = -10000.0f;
            if (v2base && mask[b * Sc + p2] != 0) bias2 = -10000.0f;
        }
        float alpha8[8];
        #pragma unroll
        for (int rr = 0; rr < 8; rr++) {
            const int r = wrp * 8 + rr;
            float s1 = KPs[r * 64 + c1];
            float s2 = KPs[r * 64 + c2];
            bool bv1 = v1base, bv2 = v2base;
            if (!is_sel) {
                const int qi = q0 + r;
                const int p1 = tstart + c1, p2 = tstart + c2;
                bv1 = v1base && (p1 >= qi - Wc) && (p1 <= qi + Wc);
                bv2 = v2base && (p2 >= qi - Wc) && (p2 <= qi + Wc);
            }
            s1 = bv1 ? (s1 + bias1) : NEG_INF;
            s2 = bv2 ? (s2 + bias2) : NEG_INF;
            float tmax = fmaxf(s1, s2);
            #pragma unroll
            for (int o = 16; o; o >>= 1) tmax = fmaxf(tmax, __shfl_xor_sync(0xffffffffu, tmax, o));
            const float mnew = fmaxf(m8[rr], tmax);
            const float a = __expf(m8[rr] - mnew);
            const float p1e = __expf(s1 - mnew);
            const float p2e = __expf(s2 - mnew);
            KPs[r * 64 + c1] = p1e;
            KPs[r * 64 + c2] = p2e;
            float tsum = p1e + p2e;
            #pragma unroll
            for (int o = 16; o; o >>= 1) tsum += __shfl_xor_sync(0xffffffffu, tsum, o);
            l8[rr] = l8[rr] * a + tsum;
            m8[rr] = mnew;
            alpha8[rr] = a;
        }
        __syncthreads();

        // PV: O = O*alpha + P @ V
        #pragma unroll
        for (int i = 0; i < 4; i++) {
            const float a = (ty & 1) ? alpha8[i + 4] : alpha8[i];
            #pragma unroll
            for (int j = 0; j < 4; j++) O[i][j] *= a;
        }
        #pragma unroll
        for (int c = 0; c < 64; c++) {
            float4 v4 = *(const float4*)&Vs[c * 64 + tx * 4];
            #pragma unroll
            for (int i = 0; i < 4; i++) {
                const float pv = KPs[(ty * 4 + i) * 64 + c];
                O[i][0] += pv * v4.x;
                O[i][1] += pv * v4.y;
                O[i][2] += pv * v4.z;
                O[i][3] += pv * v4.w;
            }
        }
    }

    // finalize
    #pragma unroll
    for (int i = 0; i < 4; i++) {
        const float linv = 1.0f / ((ty & 1) ? l8[i + 4] : l8[i]);
        float4 o4 = make_float4(O[i][0] * linv, O[i][1] * linv, O[i][2] * linv, O[i][3] * linv);
        *(float4*)&out[(size_t)(b * Sc + q0 + ty * 4 + i) * Ec + h * 64 + tx * 4] = o4;
    }
}

// ---------------- 4) global scores: gw[b,h,g,s] = qg . kg ----------------
__global__ __launch_bounds__(256) void global_scores()
{
    const int st = blockIdx.x;     // s-tile of 128
    const int h  = blockIdx.y;
    const int b  = blockIdx.z;
    __shared__ float qgs[64 * 32];   // [d][g]
    __shared__ float kgs[64 * 128];  // [d][c]
    const int t = threadIdx.x;
    {
        const int g = t >> 3, d0 = (t & 7) * 8;
        const float* qp = g_qg + (size_t)(b * Gc + g) * Ec + h * 64 + d0;
        float4 v0 = *(const float4*)qp;
        float4 v1 = *(const float4*)(qp + 4);
        qgs[(d0 + 0) * 32 + g] = v0.x; qgs[(d0 + 1) * 32 + g] = v0.y;
        qgs[(d0 + 2) * 32 + g] = v0.z; qgs[(d0 + 3) * 32 + g] = v0.w;
        qgs[(d0 + 4) * 32 + g] = v1.x; qgs[(d0 + 5) * 32 + g] = v1.y;
        qgs[(d0 + 6) * 32 + g] = v1.z; qgs[(d0 + 7) * 32 + g] = v1.w;
    }
    {
        const int c = t >> 1, d0 = (t & 1) * 32;
        const int p = st * 128 + c;
        const float* kp = g_kg + (size_t)(b * Sc + p) * Ec + h * 64 + d0;
        #pragma unroll
        for (int u = 0; u < 8; u++) {
            float4 v = *(const float4*)(kp + 4 * u);
            kgs[(d0 + 4 * u + 0) * 128 + c] = v.x;
            kgs[(d0 + 4 * u + 1) * 128 + c] = v.y;
            kgs[(d0 + 4 * u + 2) * 128 + c] = v.z;
            kgs[(d0 + 4 * u + 3) * 128 + c] = v.w;
        }
    }
    __syncthreads();
    const int tx = t & 31, ty = t >> 5;  // g=4ty..+4, s=4tx..+4
    float s[4][4];
    #pragma unroll
    for (int i = 0; i < 4; i++)
      #pragma unroll
      for (int j = 0; j < 4; j++) s[i][j] = 0.0f;
    #pragma unroll
    for (int d = 0; d < 64; d++) {
        float4 q4 = *(const float4*)&qgs[d * 32 + ty * 4];
        float4 k4 = *(const float4*)&kgs[d * 128 + tx * 4];
        float qa[4] = {q4.x, q4.y, q4.z, q4.w};
        float ka[4] = {k4.x, k4.y, k4.z, k4.w};
        #pragma unroll
        for (int i = 0; i < 4; i++)
          #pragma unroll
          for (int j = 0; j < 4; j++) s[i][j] += qa[i] * ka[j];
    }
    #pragma unroll
    for (int i = 0; i < 4; i++) {
        const int g = ty * 4 + i;
        float* gp = g_gw + (((size_t)(b * Hc + h) * Gc + g) * Sc) + st * 128 + tx * 4;
        *(float4*)gp = make_float4(s[i][0], s[i][1], s[i][2], s[i][3]);
    }
}

// ---------------- 5) row softmax over S for gw ----------------
__global__ __launch_bounds__(256) void global_softmax()
{
    float* p = g_gw + (size_t)blockIdx.x * Sc;
    __shared__ float sm[8];
    const int t = threadIdx.x, lane = t & 31, wrp = t >> 5;
    float mx = NEG_INF;
    for (int i = t; i < Sc; i += 256) mx = fmaxf(mx, p[i]);
    #pragma unroll
    for (int o = 16; o; o >>= 1) mx = fmaxf(mx, __shfl_xor_sync(0xffffffffu, mx, o));
    if (lane == 0) sm[wrp] = mx;
    __syncthreads();
    mx = sm[0];
    #pragma unroll
    for (int i = 1; i < 8; i++) mx = fmaxf(mx, sm[i]);
    __syncthreads();
    float sum = 0.0f;
    for (int i = t; i < Sc; i += 256) {
        const float e = __expf(p[i] - mx);
        p[i] = e;
        sum += e;
    }
    #pragma unroll
    for (int o = 16; o; o >>= 1) sum += __shfl_xor_sync(0xffffffffu, sum, o);
    if (lane == 0) sm[wrp] = sum;
    __syncthreads();
    sum = 0.0f;
    #pragma unroll
    for (int i = 0; i < 8; i++) sum += sm[i];
    const float inv = 1.0f / sum;
    for (int i = t; i < Sc; i += 256) p[i] *= inv;
}

// ---------------- 6) zero gattn accumulator ----------------
__global__ void zero_gattn()
{
    const int idx = blockIdx.x * 256 + threadIdx.x;
    if (idx < Bc * Gc * Ec) g_gattn[idx] = 0.0f;
}

// ---------------- 7) global PV: gattn += gp @ vg (split-S, atomic combine) ----------------
__global__ __launch_bounds__(256) void global_pv()
{
    const int sc = blockIdx.x;   // 0..7 chunk of 512 keys
    const int h  = blockIdx.y;
    const int b  = blockIdx.z;
    __shared__ float ps[32 * 128];
    const int t  = threadIdx.x;
    const int d  = t & 63;
    const int gq = t >> 6;       // 0..3 -> g = gq*8 + gi
    float acc[8];
    #pragma unroll
    for (int gi = 0; gi < 8; gi++) acc[gi] = 0.0f;

    for (int s0 = sc * 512; s0 < sc * 512 + 512; s0 += 128) {
        __syncthreads();
        {
            const int g = t >> 3, sl = (t & 7) * 16;
            const float* src = g_gw + ((size_t)(b * Hc + h) * Gc + g) * Sc + s0 + sl;
            #pragma unroll
            for (int u = 0; u < 4; u++)
                *(float4*)&ps[g * 128 + sl + 4 * u] = *(const float4*)(src + 4 * u);
        }
        __syncthreads();
        for (int sl = 0; sl < 128; sl++) {
            const float vv = g_vg[(size_t)(b * Sc + s0 + sl) * Ec + h * 64 + d];
            #pragma unroll
            for (int gi = 0; gi < 8; gi++)
                acc[gi] += ps[(gq * 8 + gi) * 128 + sl] * vv;
        }
    }
    #pragma unroll
    for (int gi = 0; gi < 8; gi++)
        atomicAdd(&g_gattn[(size_t)(b * Gc + gq * 8 + gi) * Ec + h * 64 + d], acc[gi]);
}

// ---------------- 8) overwrite out[:, :G] with gattn ----------------
__global__ void write_global_rows(float* __restrict__ out)
{
    const int idx = blockIdx.x * 256 + threadIdx.x;
    if (idx < Bc * Gc * Ec) {
        const int e = idx % Ec;
        const int m = idx / Ec;
        const int b = m / Gc, g = m % Gc;
        out[(size_t)(b * Sc + g) * Ec + e] = g_gattn[idx];
    }
}

// ---------------- launch ----------------
extern "C" void kernel_launch(void* const* d_in, const int* in_sizes, int n_in,
                              void* d_out, int out_size)
{
    (void)out_size;
    const float* x    = (const float*)d_in[0];
    const int*   mask = (const int*)d_in[1];
    // layer_id may or may not be materialized as a size-1 input
    int wi = 2;
    if (n_in > 2 && in_sizes[2] == 1) wi = 3;
    const float* wq  = (const float*)d_in[wi + 0];
    const float* bq  = (const float*)d_in[wi + 1];
    const float* wk  = (const float*)d_in[wi + 2];
    const float* bk  = (const float*)d_in[wi + 3];
    const float* wv  = (const float*)d_in[wi + 4];
    const float* bv  = (const float*)d_in[wi + 5];
    const float* wqg = (const float*)d_in[wi + 6];
    const float* bqg = (const float*)d_in[wi + 7];
    const float* wkg = (const float*)d_in[wi + 8];
    const float* bkg = (const float*)d_in[wi + 9];
    const float* wvg = (const float*)d_in[wi + 10];
    const float* bvg = (const float*)d_in[wi + 11];
    float* out = (float*)d_out;

    dim3 gGemm(Ec / 128, Mrows / 128, 5);
    proj_tf32<<<gGemm, 256>>>(x, wq, bq, wk, bk, wv, bv, wkg, bkg, wvg, bvg);
    qg_gemm<<<Bc * Gc, 256>>>(x, wqg, bqg);

    dim3 gF(Sc / 64, Hc, Bc);
    flash_banded<<<gF, 256>>>(mask, out);

    dim3 gGS(Sc / 128, Hc, Bc);
    global_scores<<<gGS, 256>>>();
    global_softmax<<<Bc * Hc * Gc, 256>>>();
    zero_gattn<<<(Bc * Gc * Ec + 255) / 256, 256>>>();
    dim3 gPV(8, Hc, Bc);
    global_pv<<<gPV, 256>>>();
    write_global_rows<<<(Bc * Gc * Ec + 255) / 256, 256>>>(out);
}

// round 8
// speedup vs baseline: 1.2855x; 1.2855x over previous
#include <cuda_runtime.h>
#include <cuda_bf16.h>
#include <stdint.h>

#define NEG_INF (__int_as_float(0xff800000))

#define Bc 2
#define Sc 4096
#define Ec 768
#define Hc 12
#define HDc 64
#define Wc 256
#define Gc 32
#define Mrows (Bc*Sc)   /* 8192 */

// ---------------- scratch (device globals; no allocation allowed) ----------------
__device__ float g_q [Mrows*Ec];
__device__ float g_k [Mrows*Ec];
__device__ float g_v [Mrows*Ec];
__device__ float g_kg[Mrows*Ec];
__device__ float g_vg[Mrows*Ec];
__device__ float g_qg[Bc*Gc*Ec];
__device__ float g_gw[(size_t)Bc*Hc*Gc*Sc];
__device__ float g_gattn[Bc*Gc*Ec];

// bf16 split scratch (uint4 arrays for guaranteed 16B alignment)
__device__ uint4 g_xh4[(size_t)Mrows*Ec/8];
__device__ uint4 g_xl4[(size_t)Mrows*Ec/8];
__device__ uint4 g_wth4[(size_t)5*Ec*Ec/8];
__device__ uint4 g_wtl4[(size_t)5*Ec*Ec/8];

// ---------------- bf16 mma helper (legacy mma.sync, valid on compute_103) ----------------
__device__ __forceinline__ void mma_bf16(float* d, const uint32_t* a, const uint32_t* b) {
    asm volatile(
        "mma.sync.aligned.m16n8k16.row.col.f32.bf16.bf16.f32 "
        "{%0,%1,%2,%3},{%4,%5,%6,%7},{%8,%9},{%0,%1,%2,%3};"
        : "+f"(d[0]), "+f"(d[1]), "+f"(d[2]), "+f"(d[3])
        : "r"(a[0]), "r"(a[1]), "r"(a[2]), "r"(a[3]), "r"(b[0]), "r"(b[1]));
}

// ---------------- 0a) split x -> bf16 hi/lo ----------------
__global__ __launch_bounds__(256) void split_x(const float* __restrict__ x)
{
    const int i = (blockIdx.x * 256 + threadIdx.x) * 4;
    float4 v = *(const float4*)&x[i];
    __nv_bfloat16 hx = __float2bfloat16_rn(v.x);
    __nv_bfloat16 hy = __float2bfloat16_rn(v.y);
    __nv_bfloat16 hz = __float2bfloat16_rn(v.z);
    __nv_bfloat16 hw = __float2bfloat16_rn(v.w);
    __nv_bfloat16 lx = __float2bfloat16_rn(v.x - __bfloat162float(hx));
    __nv_bfloat16 ly = __float2bfloat16_rn(v.y - __bfloat162float(hy));
    __nv_bfloat16 lz = __float2bfloat16_rn(v.z - __bfloat162float(hz));
    __nv_bfloat16 lw = __float2bfloat16_rn(v.w - __bfloat162float(hw));
    __nv_bfloat162* ph = (__nv_bfloat162*)g_xh4;
    __nv_bfloat162* pl = (__nv_bfloat162*)g_xl4;
    ph[i/2]     = __nv_bfloat162(hx, hy);
    ph[i/2 + 1] = __nv_bfloat162(hz, hw);
    pl[i/2]     = __nv_bfloat162(lx, ly);
    pl[i/2 + 1] = __nv_bfloat162(lz, lw);
}

// ---------------- 0b) transpose + split W -> wT[n][k] bf16 hi/lo ----------------
__global__ __launch_bounds__(256) void split_wt(
    const float* __restrict__ w0, const float* __restrict__ w1,
    const float* __restrict__ w2, const float* __restrict__ w3,
    const float* __restrict__ w4)
{
    const int z = blockIdx.z;
    const float* W;
    switch (z) {
      case 0: W = w0; break; case 1: W = w1; break; case 2: W = w2; break;
      case 3: W = w3; break; default: W = w4; break;
    }
    __shared__ float tile[32][33];
    const int k0 = blockIdx.x * 32;
    const int n0 = blockIdx.y * 32;
    const int t = threadIdx.x;
    const int tx = t & 31, ty = t >> 5;
    #pragma unroll
    for (int i = 0; i < 4; i++)
        tile[ty + 8*i][tx] = W[(size_t)(k0 + ty + 8*i) * Ec + n0 + tx];
    __syncthreads();
    __nv_bfloat16* oh = (__nv_bfloat16*)g_wth4 + (size_t)z * Ec * Ec;
    __nv_bfloat16* ol = (__nv_bfloat16*)g_wtl4 + (size_t)z * Ec * Ec;
    #pragma unroll
    for (int i = 0; i < 4; i++) {
        const float v = tile[tx][ty + 8*i];
        const __nv_bfloat16 h = __float2bfloat16_rn(v);
        const __nv_bfloat16 l = __float2bfloat16_rn(v - __bfloat162float(h));
        oh[(size_t)(n0 + ty + 8*i) * Ec + k0 + tx] = h;
        ol[(size_t)(n0 + ty + 8*i) * Ec + k0 + tx] = l;
    }
}

// ---------------- 1) projection GEMMs: bf16 m16n8k16 3-term split ----------------
// C[8192,768] = (A @ W + bias) * scale; 128x128 tile, 8 warps (2m x 4n), warp 64x32.
// smem: k-pair packed uint32 [16][SSTR2] per array (k-tile 32 = 16 kpairs).
#define SSTR2 136   /* 136 % 32 == 8 -> banks 8*tig+gid all distinct */
#define KT 32

__global__ __launch_bounds__(256) void proj_bf16(
    const float* __restrict__ b0, const float* __restrict__ b1,
    const float* __restrict__ b2, const float* __restrict__ b3,
    const float* __restrict__ b4)
{
    const int z  = blockIdx.z;
    const float* bias; float* out; float scale = 1.0f;
    switch (z) {
      case 0: bias = b0; out = g_q;  scale = 0.125f; break;
      case 1: bias = b1; out = g_k;  break;
      case 2: bias = b2; out = g_v;  break;
      case 3: bias = b3; out = g_kg; break;
      default:bias = b4; out = g_vg; break;
    }
    const int m0 = blockIdx.y * 128;
    const int n0 = blockIdx.x * 128;

    const char* Axh = (const char*)g_xh4;
    const char* Axl = (const char*)g_xl4;
    const char* Bwh = (const char*)g_wth4 + (size_t)z * Ec * Ec * 2;
    const char* Bwl = (const char*)g_wtl4 + (size_t)z * Ec * Ec * 2;

    __shared__ uint32_t Ah2[16][SSTR2];
    __shared__ uint32_t Al2[16][SSTR2];
    __shared__ uint32_t Bh2[16][SSTR2];
    __shared__ uint32_t Bl2[16][SSTR2];

    const int t    = threadIdx.x;
    const int lane = t & 31;
    const int warp = t >> 5;
    const int gid  = lane >> 2;    // 0..7
    const int tig  = lane & 3;     // 0..3
    const int mbase = (warp & 1) * 64;
    const int nbase = (warp >> 1) * 32;

    // global load slots: slot s in {t, t+256}; row = s>>2 (0..127), kq = s&3
    const int r0 = t >> 2,        kq0 = t & 3;
    const int r1 = (t + 256) >> 2, kq1 = (t + 256) & 3;

    const char* pAh0 = Axh + ((size_t)(m0 + r0) * Ec + kq0 * 8) * 2;
    const char* pAh1 = Axh + ((size_t)(m0 + r1) * Ec + kq1 * 8) * 2;
    const char* pAl0 = Axl + ((size_t)(m0 + r0) * Ec + kq0 * 8) * 2;
    const char* pAl1 = Axl + ((size_t)(m0 + r1) * Ec + kq1 * 8) * 2;
    const char* pBh0 = Bwh + ((size_t)(n0 + r0) * Ec + kq0 * 8) * 2;
    const char* pBh1 = Bwh + ((size_t)(n0 + r1) * Ec + kq1 * 8) * 2;
    const char* pBl0 = Bwl + ((size_t)(n0 + r0) * Ec + kq0 * 8) * 2;
    const char* pBl1 = Bwl + ((size_t)(n0 + r1) * Ec + kq1 * 8) * 2;

    float acc[4][4][4];
    #pragma unroll
    for (int mt = 0; mt < 4; mt++)
      #pragma unroll
      for (int nt = 0; nt < 4; nt++)
        #pragma unroll
        for (int i = 0; i < 4; i++) acc[mt][nt][i] = 0.0f;

    uint4 vAh0 = *(const uint4*)pAh0, vAh1 = *(const uint4*)pAh1;
    uint4 vAl0 = *(const uint4*)pAl0, vAl1 = *(const uint4*)pAl1;
    uint4 vBh0 = *(const uint4*)pBh0, vBh1 = *(const uint4*)pBh1;
    uint4 vBl0 = *(const uint4*)pBl0, vBl1 = *(const uint4*)pBl1;

    for (int kt = 0; kt < Ec; kt += KT) {
        __syncthreads();
        {
            const int rr0 = kq0 * 4, rr1 = kq1 * 4;
            Ah2[rr0 + 0][r0] = vAh0.x; Ah2[rr0 + 1][r0] = vAh0.y;
            Ah2[rr0 + 2][r0] = vAh0.z; Ah2[rr0 + 3][r0] = vAh0.w;
            Ah2[rr1 + 0][r1] = vAh1.x; Ah2[rr1 + 1][r1] = vAh1.y;
            Ah2[rr1 + 2][r1] = vAh1.z; Ah2[rr1 + 3][r1] = vAh1.w;
            Al2[rr0 + 0][r0] = vAl0.x; Al2[rr0 + 1][r0] = vAl0.y;
            Al2[rr0 + 2][r0] = vAl0.z; Al2[rr0 + 3][r0] = vAl0.w;
            Al2[rr1 + 0][r1] = vAl1.x; Al2[rr1 + 1][r1] = vAl1.y;
            Al2[rr1 + 2][r1] = vAl1.z; Al2[rr1 + 3][r1] = vAl1.w;
            Bh2[rr0 + 0][r0] = vBh0.x; Bh2[rr0 + 1][r0] = vBh0.y;
            Bh2[rr0 + 2][r0] = vBh0.z; Bh2[rr0 + 3][r0] = vBh0.w;
            Bh2[rr1 + 0][r1] = vBh1.x; Bh2[rr1 + 1][r1] = vBh1.y;
            Bh2[rr1 + 2][r1] = vBh1.z; Bh2[rr1 + 3][r1] = vBh1.w;
            Bl2[rr0 + 0][r0] = vBl0.x; Bl2[rr0 + 1][r0] = vBl0.y;
            Bl2[rr0 + 2][r0] = vBl0.z; Bl2[rr0 + 3][r0] = vBl0.w;
            Bl2[rr1 + 0][r1] = vBl1.x; Bl2[rr1 + 1][r1] = vBl1.y;
            Bl2[rr1 + 2][r1] = vBl1.z; Bl2[rr1 + 3][r1] = vBl1.w;
        }
        __syncthreads();

        if (kt + KT < Ec) {
            const int koff = (kt + KT) * 2;
            vAh0 = *(const uint4*)(pAh0 + koff); vAh1 = *(const uint4*)(pAh1 + koff);
            vAl0 = *(const uint4*)(pAl0 + koff); vAl1 = *(const uint4*)(pAl1 + koff);
            vBh0 = *(const uint4*)(pBh0 + koff); vBh1 = *(const uint4*)(pBh1 + koff);
            vBl0 = *(const uint4*)(pBl0 + koff); vBl1 = *(const uint4*)(pBl1 + koff);
        }

        #pragma unroll
        for (int s16 = 0; s16 < 2; s16++) {
            const int kb = s16 * 8;
            uint32_t ah[4][4], al[4][4], bh[4][2], bl[4][2];
            #pragma unroll
            for (int mt = 0; mt < 4; mt++) {
                const int m = mbase + mt * 16 + gid;
                ah[mt][0] = Ah2[kb + tig][m];
                ah[mt][1] = Ah2[kb + tig][m + 8];
                ah[mt][2] = Ah2[kb + tig + 4][m];
                ah[mt][3] = Ah2[kb + tig + 4][m + 8];
                al[mt][0] = Al2[kb + tig][m];
                al[mt][1] = Al2[kb + tig][m + 8];
                al[mt][2] = Al2[kb + tig + 4][m];
                al[mt][3] = Al2[kb + tig + 4][m + 8];
            }
            #pragma unroll
            for (int nt = 0; nt < 4; nt++) {
                const int n = nbase + nt * 8 + gid;
                bh[nt][0] = Bh2[kb + tig][n];
                bh[nt][1] = Bh2[kb + tig + 4][n];
                bl[nt][0] = Bl2[kb + tig][n];
                bl[nt][1] = Bl2[kb + tig + 4][n];
            }
            #pragma unroll
            for (int mt = 0; mt < 4; mt++)
              #pragma unroll
              for (int nt = 0; nt < 4; nt++) {
                  mma_bf16(acc[mt][nt], ah[mt], bh[nt]);
                  mma_bf16(acc[mt][nt], ah[mt], bl[nt]);
                  mma_bf16(acc[mt][nt], al[mt], bh[nt]);
              }
        }
    }

    // epilogue: bias + scale (m16n8 C layout: c0,c1 row gid; c2,c3 row gid+8)
    #pragma unroll
    for (int mt = 0; mt < 4; mt++) {
        const int r = m0 + mbase + mt * 16 + gid;
        #pragma unroll
        for (int nt = 0; nt < 4; nt++) {
            const int c = n0 + nbase + nt * 8 + 2 * tig;
            const float bb0 = bias[c], bb1 = bias[c + 1];
            float2 o0 = make_float2((acc[mt][nt][0] + bb0) * scale,
                                    (acc[mt][nt][1] + bb1) * scale);
            float2 o1 = make_float2((acc[mt][nt][2] + bb0) * scale,
                                    (acc[mt][nt][3] + bb1) * scale);
            *(float2*)&out[(size_t)r * Ec + c] = o0;
            *(float2*)&out[(size_t)(r + 8) * Ec + c] = o1;
        }
    }
}

// ---------------- 2) qg (tiny GEMM over first G rows of each batch) ----------------
__global__ __launch_bounds__(256) void qg_gemm(const float* __restrict__ x,
                                               const float* __restrict__ w,
                                               const float* __restrict__ bias)
{
    const int m = blockIdx.x;           // 0..63
    const int b = m >> 5, g = m & 31;
    const float* xr = x + (size_t)(b * Sc + g) * Ec;
    __shared__ float xs[Ec];
    const int t = threadIdx.x;
    xs[t] = xr[t]; xs[t + 256] = xr[t + 256]; xs[t + 512] = xr[t + 512];
    __syncthreads();
    float a0 = 0.f, a1 = 0.f, a2 = 0.f;
    for (int k = 0; k < Ec; k++) {
        const float xv = xs[k];
        const float* wr = w + (size_t)k * Ec;
        a0 += xv * wr[t];
        a1 += xv * wr[t + 256];
        a2 += xv * wr[t + 512];
    }
    float* o = g_qg + (size_t)m * Ec;
    o[t]       = (a0 + bias[t])       * 0.125f;
    o[t + 256] = (a1 + bias[t + 256]) * 0.125f;
    o[t + 512] = (a2 + bias[t + 512]) * 0.125f;
}

// ---------------- 3) banded + global flash attention ----------------
__global__ __launch_bounds__(256) void flash_banded(const int* __restrict__ mask,
                                                    float* __restrict__ out)
{
    const int q0 = blockIdx.x * 64;
    const int h  = blockIdx.y;
    const int b  = blockIdx.z;

    __shared__ float Qs[64 * 64];   // [d][r]
    __shared__ float KPs[64 * 64];  // K as [d][c], then reused as P [r][c]
    __shared__ float Vs[64 * 64];   // [c][d]

    const int t    = threadIdx.x;
    const int tx   = t & 15, ty = t >> 4;
    const int lane = t & 31, wrp = t >> 5;

    {
        const int lr = t >> 2, ld = (t & 3) * 16;
        const float* qp = g_q + (size_t)(b * Sc + q0 + lr) * Ec + h * 64 + ld;
        #pragma unroll
        for (int u = 0; u < 4; u++) {
            float4 v = *(const float4*)(qp + 4 * u);
            Qs[(ld + 4 * u + 0) * 64 + lr] = v.x;
            Qs[(ld + 4 * u + 1) * 64 + lr] = v.y;
            Qs[(ld + 4 * u + 2) * 64 + lr] = v.z;
            Qs[(ld + 4 * u + 3) * 64 + lr] = v.w;
        }
    }

    float m8[8], l8[8];
    #pragma unroll
    for (int i = 0; i < 8; i++) { m8[i] = NEG_INF; l8[i] = 0.0f; }
    float O[4][4];
    #pragma unroll
    for (int i = 0; i < 4; i++)
      #pragma unroll
      for (int j = 0; j < 4; j++) O[i][j] = 0.0f;

    for (int tt = 0; tt < 10; tt++) {
        const bool is_sel = (tt == 0);
        const int tstart = is_sel ? 0 : (q0 - Wc + (tt - 1) * 64);

        __syncthreads();
        {
            const int lr = t >> 2, ld = (t & 3) * 16;
            const int p = tstart + lr;
            if (p >= 0 && p < Sc) {
                const float* kp = g_k + (size_t)(b * Sc + p) * Ec + h * 64 + ld;
                const float* vp = g_v + (size_t)(b * Sc + p) * Ec + h * 64 + ld;
                #pragma unroll
                for (int u = 0; u < 4; u++) {
                    float4 kv = *(const float4*)(kp + 4 * u);
                    KPs[(ld + 4 * u + 0) * 64 + lr] = kv.x;
                    KPs[(ld + 4 * u + 1) * 64 + lr] = kv.y;
                    KPs[(ld + 4 * u + 2) * 64 + lr] = kv.z;
                    KPs[(ld + 4 * u + 3) * 64 + lr] = kv.w;
                    *(float4*)&Vs[lr * 64 + ld + 4 * u] = *(const float4*)(vp + 4 * u);
                }
            } else {
                const float4 z4 = make_float4(0.f, 0.f, 0.f, 0.f);
                #pragma unroll
                for (int u = 0; u < 4; u++) {
                    KPs[(ld + 4 * u + 0) * 64 + lr] = 0.f;
                    KPs[(ld + 4 * u + 1) * 64 + lr] = 0.f;
                    KPs[(ld + 4 * u + 2) * 64 + lr] = 0.f;
                    KPs[(ld + 4 * u + 3) * 64 + lr] = 0.f;
                    *(float4*)&Vs[lr * 64 + ld + 4 * u] = z4;
                }
            }
        }
        __syncthreads();

        float s[4][4];
        #pragma unroll
        for (int i = 0; i < 4; i++)
          #pragma unroll
          for (int j = 0; j < 4; j++) s[i][j] = 0.0f;
        #pragma unroll
        for (int d = 0; d < 64; d++) {
            float4 q4 = *(const float4*)&Qs[d * 64 + ty * 4];
            float4 k4 = *(const float4*)&KPs[d * 64 + tx * 4];
            float qa[4] = {q4.x, q4.y, q4.z, q4.w};
            float ka[4] = {k4.x, k4.y, k4.z, k4.w};
            #pragma unroll
            for (int i = 0; i < 4; i++)
              #pragma unroll
              for (int j = 0; j < 4; j++) s[i][j] += qa[i] * ka[j];
        }
        __syncthreads();
        #pragma unroll
        for (int i = 0; i < 4; i++)
            *(float4*)&KPs[(ty * 4 + i) * 64 + tx * 4] =
                make_float4(s[i][0], s[i][1], s[i][2], s[i][3]);
        __syncthreads();

        const int c1 = lane, c2 = lane + 32;
        float bias1 = 0.f, bias2 = 0.f;
        bool v1base, v2base;
        if (is_sel) {
            v1base = (c1 < Gc);
            v2base = false;
        } else {
            const int p1 = tstart + c1, p2 = tstart + c2;
            v1base = (p1 >= 0 && p1 < Sc);
            v2base = (p2 >= 0 && p2 < Sc);
            if (v1base && mask[b * Sc + p1] != 0) bias1 = -10000.0f;
            if (v2base && mask[b * Sc + p2] != 0) bias2 = -10000.0f;
        }
        float alpha8[8];
        #pragma unroll
        for (int rr = 0; rr < 8; rr++) {
            const int r = wrp * 8 + rr;
            float s1 = KPs[r * 64 + c1];
            float s2 = KPs[r * 64 + c2];
            bool bv1 = v1base, bv2 = v2base;
            if (!is_sel) {
                const int qi = q0 + r;
                const int p1 = tstart + c1, p2 = tstart + c2;
                bv1 = v1base && (p1 >= qi - Wc) && (p1 <= qi + Wc);
                bv2 = v2base && (p2 >= qi - Wc) && (p2 <= qi + Wc);
            }
            s1 = bv1 ? (s1 + bias1) : NEG_INF;
            s2 = bv2 ? (s2 + bias2) : NEG_INF;
            float tmax = fmaxf(s1, s2);
            #pragma unroll
            for (int o = 16; o; o >>= 1) tmax = fmaxf(tmax, __shfl_xor_sync(0xffffffffu, tmax, o));
            const float mnew = fmaxf(m8[rr], tmax);
            const float a = __expf(m8[rr] - mnew);
            const float p1e = __expf(s1 - mnew);
            const float p2e = __expf(s2 - mnew);
            KPs[r * 64 + c1] = p1e;
            KPs[r * 64 + c2] = p2e;
            float tsum = p1e + p2e;
            #pragma unroll
            for (int o = 16; o; o >>= 1) tsum += __shfl_xor_sync(0xffffffffu, tsum, o);
            l8[rr] = l8[rr] * a + tsum;
            m8[rr] = mnew;
            alpha8[rr] = a;
        }
        __syncthreads();

        #pragma unroll
        for (int i = 0; i < 4; i++) {
            const float a = (ty & 1) ? alpha8[i + 4] : alpha8[i];
            #pragma unroll
            for (int j = 0; j < 4; j++) O[i][j] *= a;
        }
        #pragma unroll
        for (int c = 0; c < 64; c++) {
            float4 v4 = *(const float4*)&Vs[c * 64 + tx * 4];
            #pragma unroll
            for (int i = 0; i < 4; i++) {
                const float pv = KPs[(ty * 4 + i) * 64 + c];
                O[i][0] += pv * v4.x;
                O[i][1] += pv * v4.y;
                O[i][2] += pv * v4.z;
                O[i][3] += pv * v4.w;
            }
        }
    }

    #pragma unroll
    for (int i = 0; i < 4; i++) {
        const float linv = 1.0f / ((ty & 1) ? l8[i + 4] : l8[i]);
        float4 o4 = make_float4(O[i][0] * linv, O[i][1] * linv, O[i][2] * linv, O[i][3] * linv);
        *(float4*)&out[(size_t)(b * Sc + q0 + ty * 4 + i) * Ec + h * 64 + tx * 4] = o4;
    }
}

// ---------------- 4) global scores ----------------
__global__ __launch_bounds__(256) void global_scores()
{
    const int st = blockIdx.x;
    const int h  = blockIdx.y;
    const int b  = blockIdx.z;
    __shared__ float qgs[64 * 32];
    __shared__ float kgs[64 * 128];
    const int t = threadIdx.x;
    {
        const int g = t >> 3, d0 = (t & 7) * 8;
        const float* qp = g_qg + (size_t)(b * Gc + g) * Ec + h * 64 + d0;
        float4 v0 = *(const float4*)qp;
        float4 v1 = *(const float4*)(qp + 4);
        qgs[(d0 + 0) * 32 + g] = v0.x; qgs[(d0 + 1) * 32 + g] = v0.y;
        qgs[(d0 + 2) * 32 + g] = v0.z; qgs[(d0 + 3) * 32 + g] = v0.w;
        qgs[(d0 + 4) * 32 + g] = v1.x; qgs[(d0 + 5) * 32 + g] = v1.y;
        qgs[(d0 + 6) * 32 + g] = v1.z; qgs[(d0 + 7) * 32 + g] = v1.w;
    }
    {
        const int c = t >> 1, d0 = (t & 1) * 32;
        const int p = st * 128 + c;
        const float* kp = g_kg + (size_t)(b * Sc + p) * Ec + h * 64 + d0;
        #pragma unroll
        for (int u = 0; u < 8; u++) {
            float4 v = *(const float4*)(kp + 4 * u);
            kgs[(d0 + 4 * u + 0) * 128 + c] = v.x;
            kgs[(d0 + 4 * u + 1) * 128 + c] = v.y;
            kgs[(d0 + 4 * u + 2) * 128 + c] = v.z;
            kgs[(d0 + 4 * u + 3) * 128 + c] = v.w;
        }
    }
    __syncthreads();
    const int tx = t & 31, ty = t >> 5;
    float s[4][4];
    #pragma unroll
    for (int i = 0; i < 4; i++)
      #pragma unroll
      for (int j = 0; j < 4; j++) s[i][j] = 0.0f;
    #pragma unroll
    for (int d = 0; d < 64; d++) {
        float4 q4 = *(const float4*)&qgs[d * 32 + ty * 4];
        float4 k4 = *(const float4*)&kgs[d * 128 + tx * 4];
        float qa[4] = {q4.x, q4.y, q4.z, q4.w};
        float ka[4] = {k4.x, k4.y, k4.z, k4.w};
        #pragma unroll
        for (int i = 0; i < 4; i++)
          #pragma unroll
          for (int j = 0; j < 4; j++) s[i][j] += qa[i] * ka[j];
    }
    #pragma unroll
    for (int i = 0; i < 4; i++) {
        const int g = ty * 4 + i;
        float* gp = g_gw + (((size_t)(b * Hc + h) * Gc + g) * Sc) + st * 128 + tx * 4;
        *(float4*)gp = make_float4(s[i][0], s[i][1], s[i][2], s[i][3]);
    }
}

// ---------------- 5) row softmax over S for gw ----------------
__global__ __launch_bounds__(256) void global_softmax()
{
    float* p = g_gw + (size_t)blockIdx.x * Sc;
    __shared__ float sm[8];
    const int t = threadIdx.x, lane = t & 31, wrp = t >> 5;
    float mx = NEG_INF;
    for (int i = t; i < Sc; i += 256) mx = fmaxf(mx, p[i]);
    #pragma unroll
    for (int o = 16; o; o >>= 1) mx = fmaxf(mx, __shfl_xor_sync(0xffffffffu, mx, o));
    if (lane == 0) sm[wrp] = mx;
    __syncthreads();
    mx = sm[0];
    #pragma unroll
    for (int i = 1; i < 8; i++) mx = fmaxf(mx, sm[i]);
    __syncthreads();
    float sum = 0.0f;
    for (int i = t; i < Sc; i += 256) {
        const float e = __expf(p[i] - mx);
        p[i] = e;
        sum += e;
    }
    #pragma unroll
    for (int o = 16; o; o >>= 1) sum += __shfl_xor_sync(0xffffffffu, sum, o);
    if (lane == 0) sm[wrp] = sum;
    __syncthreads();
    sum = 0.0f;
    #pragma unroll
    for (int i = 0; i < 8; i++) sum += sm[i];
    const float inv = 1.0f / sum;
    for (int i = t; i < Sc; i += 256) p[i] *= inv;
}

// ---------------- 6) zero gattn accumulator ----------------
__global__ void zero_gattn()
{
    const int idx = blockIdx.x * 256 + threadIdx.x;
    if (idx < Bc * Gc * Ec) g_gattn[idx] = 0.0f;
}

// ---------------- 7) global PV ----------------
__global__ __launch_bounds__(256) void global_pv()
{
    const int sc = blockIdx.x;
    const int h  = blockIdx.y;
    const int b  = blockIdx.z;
    __shared__ float ps[32 * 128];
    const int t  = threadIdx.x;
    const int d  = t & 63;
    const int gq = t >> 6;
    float acc[8];
    #pragma unroll
    for (int gi = 0; gi < 8; gi++) acc[gi] = 0.0f;

    for (int s0 = sc * 512; s0 < sc * 512 + 512; s0 += 128) {
        __syncthreads();
        {
            const int g = t >> 3, sl = (t & 7) * 16;
            const float* src = g_gw + ((size_t)(b * Hc + h) * Gc + g) * Sc + s0 + sl;
            #pragma unroll
            for (int u = 0; u < 4; u++)
                *(float4*)&ps[g * 128 + sl + 4 * u] = *(const float4*)(src + 4 * u);
        }
        __syncthreads();
        for (int sl = 0; sl < 128; sl++) {
            const float vv = g_vg[(size_t)(b * Sc + s0 + sl) * Ec + h * 64 + d];
            #pragma unroll
            for (int gi = 0; gi < 8; gi++)
                acc[gi] += ps[(gq * 8 + gi) * 128 + sl] * vv;
        }
    }
    #pragma unroll
    for (int gi = 0; gi < 8; gi++)
        atomicAdd(&g_gattn[(size_t)(b * Gc + gq * 8 + gi) * Ec + h * 64 + d], acc[gi]);
}

// ---------------- 8) overwrite out[:, :G] with gattn ----------------
__global__ void write_global_rows(float* __restrict__ out)
{
    const int idx = blockIdx.x * 256 + threadIdx.x;
    if (idx < Bc * Gc * Ec) {
        const int e = idx % Ec;
        const int m = idx / Ec;
        const int b = m / Gc, g = m % Gc;
        out[(size_t)(b * Sc + g) * Ec + e] = g_gattn[idx];
    }
}

// ---------------- launch ----------------
extern "C" void kernel_launch(void* const* d_in, const int* in_sizes, int n_in,
                              void* d_out, int out_size)
{
    (void)out_size;
    const float* x    = (const float*)d_in[0];
    const int*   mask = (const int*)d_in[1];
    int wi = 2;
    if (n_in > 2 && in_sizes[2] == 1) wi = 3;
    const float* wq  = (const float*)d_in[wi + 0];
    const float* bq  = (const float*)d_in[wi + 1];
    const float* wk  = (const float*)d_in[wi + 2];
    const float* bk  = (const float*)d_in[wi + 3];
    const float* wv  = (const float*)d_in[wi + 4];
    const float* bv  = (const float*)d_in[wi + 5];
    const float* wqg = (const float*)d_in[wi + 6];
    const float* bqg = (const float*)d_in[wi + 7];
    const float* wkg = (const float*)d_in[wi + 8];
    const float* bkg = (const float*)d_in[wi + 9];
    const float* wvg = (const float*)d_in[wi + 10];
    const float* bvg = (const float*)d_in[wi + 11];
    float* out = (float*)d_out;

    split_x<<<(Mrows * Ec) / 1024, 256>>>(x);
    split_wt<<<dim3(Ec / 32, Ec / 32, 5), 256>>>(wq, wk, wv, wkg, wvg);
    proj_bf16<<<dim3(Ec / 128, Mrows / 128, 5), 256>>>(bq, bk, bv, bkg, bvg);
    qg_gemm<<<Bc * Gc, 256>>>(x, wqg, bqg);

    dim3 gF(Sc / 64, Hc, Bc);
    flash_banded<<<gF, 256>>>(mask, out);

    dim3 gGS(Sc / 128, Hc, Bc);
    global_scores<<<gGS, 256>>>();
    global_softmax<<<Bc * Hc * Gc, 256>>>();
    zero_gattn<<<(Bc * Gc * Ec + 255) / 256, 256>>>();
    dim3 gPV(8, Hc, Bc);
    global_pv<<<gPV, 256>>>();
    write_global_rows<<<(Bc * Gc * Ec + 255) / 256, 256>>>(out);
}